// round 3
// baseline (speedup 1.0000x reference)
#include <cuda_runtime.h>
#include <cuda_bf16.h>
#include <cstdint>

#define L_HOPS 5
#define D_DIM  32
#define E_MAX  131072

#define BLOCK   128
#define PPT     4                      // pairs per thread
#define PPB     (BLOCK * PPT)          // 512 pairs per block
#define I4_PB   (PPB * L_HOPS / 4)     // 640 int4 of path_edges per block

// Precomputed dots[e][l] = <edge_vector[l], edge_attr[e]>  (2.6 MB, L2-resident)
__device__ float g_table[(size_t)E_MAX * L_HOPS];

// 1/max(len,1); len==0 -> 0 (sum is 0 anyway)
__constant__ float c_inv[8] = {0.0f, 1.0f, 0.5f, 1.0f / 3.0f, 0.25f, 0.2f, 0.0f, 0.0f};

// ---------------------------------------------------------------------------
// Kernel 1: per-(edge, hop) dot products. One thread per edge (128 B row).
// ---------------------------------------------------------------------------
__global__ void __launch_bounds__(256) precompute_dots_kernel(
    const float* __restrict__ edge_attr,   // [E, 32]
    const float* __restrict__ edge_vector, // [5, 32]
    int E)
{
    __shared__ float sev[L_HOPS * D_DIM];
    if (threadIdx.x < L_HOPS * D_DIM)
        sev[threadIdx.x] = edge_vector[threadIdx.x];
    __syncthreads();

    int e = blockIdx.x * blockDim.x + threadIdx.x;
    if (e >= E) return;

    const float4* row = reinterpret_cast<const float4*>(edge_attr + (size_t)e * D_DIM);

    float acc0 = 0.f, acc1 = 0.f, acc2 = 0.f, acc3 = 0.f, acc4 = 0.f;
#pragma unroll
    for (int i = 0; i < D_DIM / 4; i++) {
        float4 v = row[i];
#pragma unroll
        for (int c = 0; c < 4; c++) {
            float a = (c == 0) ? v.x : (c == 1) ? v.y : (c == 2) ? v.z : v.w;
            int d = i * 4 + c;
            acc0 = fmaf(a, sev[0 * D_DIM + d], acc0);
            acc1 = fmaf(a, sev[1 * D_DIM + d], acc1);
            acc2 = fmaf(a, sev[2 * D_DIM + d], acc2);
            acc3 = fmaf(a, sev[3 * D_DIM + d], acc3);
            acc4 = fmaf(a, sev[4 * D_DIM + d], acc4);
        }
    }

    float* t = g_table + (size_t)e * L_HOPS;
    t[0] = acc0; t[1] = acc1; t[2] = acc2; t[3] = acc3; t[4] = acc4;
}

// ---------------------------------------------------------------------------
// Kernel 2: 4 pairs/thread, 128 threads/block.
//   Phase A: block cooperatively loads its 640 int4 of path_edges COALESCED
//            into smem (4 wf per warp-LDG instead of ~32).
//   Phase B: each thread reads its 5 int4 back via LDS.128 (conflict-free at
//            80B lane stride), issues up to 20 predicated gathers, reduces.
// ---------------------------------------------------------------------------
__global__ void __launch_bounds__(BLOCK) pair_reduce_kernel4(
    const int* __restrict__ path_edges,  // [P, 5]
    const int* __restrict__ path_len,    // [P]
    float* __restrict__ out,             // [P]
    int Pq)                              // P / 4
{
    __shared__ int4 s_pe[I4_PB];

    int tid = threadIdx.x;
    int t   = blockIdx.x * BLOCK + tid;           // quad-pair index

    // Phase A: coalesced stage of path_edges for this block's 512 pairs.
    {
        size_t blk_i4   = (size_t)blockIdx.x * I4_PB;
        int    total_i4 = Pq * L_HOPS;            // int4 count of vector region
        const int4* gpe = reinterpret_cast<const int4*>(path_edges);
#pragma unroll
        for (int k = 0; k < I4_PB / BLOCK; k++) { // 5 iterations
            int i = tid + k * BLOCK;
            size_t gi = blk_i4 + i;
            if (gi < (size_t)total_i4)
                s_pe[i] = __ldg(gpe + gi);
        }
    }
    __syncthreads();

    if (t >= Pq) return;

    // path_len: already coalesced int4 stream.
    int4 lnv = __ldg(reinterpret_cast<const int4*>(path_len) + t);
    int len4[PPT] = {lnv.x, lnv.y, lnv.z, lnv.w};

    // Phase B: conflict-free LDS.128 readback of this thread's 20 indices.
    int idx[PPT * L_HOPS];
#pragma unroll
    for (int k = 0; k < 5; k++) {
        int4 q = s_pe[tid * 5 + k];
        idx[k * 4 + 0] = q.x;
        idx[k * 4 + 1] = q.y;
        idx[k * 4 + 2] = q.z;
        idx[k * 4 + 3] = q.w;
    }

    // Issue all predicated gathers (maximize loads in flight).
    float v[PPT * L_HOPS];
#pragma unroll
    for (int j = 0; j < PPT; j++) {
#pragma unroll
        for (int l = 0; l < L_HOPS; l++) {
            int i = j * L_HOPS + l;
            v[i] = (len4[j] > l)
                 ? __ldg(&g_table[(size_t)idx[i] * L_HOPS + l])
                 : 0.f;
        }
    }

    // Reduce + masked mean.
    float4 r;
    float* rp = &r.x;
#pragma unroll
    for (int j = 0; j < PPT; j++) {
        float s = ((v[j * 5 + 0] + v[j * 5 + 1]) + (v[j * 5 + 2] + v[j * 5 + 3]))
                + v[j * 5 + 4];
        rp[j] = s * c_inv[len4[j] & 7];
    }
    reinterpret_cast<float4*>(out)[t] = r;
}

// Scalar fallback for P not divisible by 4 (not hit for N=1024).
__global__ void pair_reduce_tail(
    const int* __restrict__ path_edges,
    const int* __restrict__ path_len,
    float* __restrict__ out,
    int start, int P)
{
    int p = start + blockIdx.x * blockDim.x + threadIdx.x;
    if (p >= P) return;
    int len = path_len[p];
    const int* row = path_edges + (size_t)p * L_HOPS;
    float s = 0.f;
#pragma unroll
    for (int l = 0; l < L_HOPS; l++)
        s += (len > l) ? __ldg(&g_table[(size_t)row[l] * L_HOPS + l]) : 0.f;
    out[p] = s * c_inv[len & 7];
}

// ---------------------------------------------------------------------------
// Inputs: x[N,32], edge_attr[E,32], edge_vector[5,32],
//         path_edges[P,5] (int32), path_len[P] (int32)  -> out float32 [P]
// ---------------------------------------------------------------------------
extern "C" void kernel_launch(void* const* d_in, const int* in_sizes, int n_in,
                              void* d_out, int out_size)
{
    const float* edge_attr   = (const float*)d_in[1];
    const float* edge_vector = (const float*)d_in[2];
    const int*   path_edges  = (const int*)d_in[3];
    const int*   path_len    = (const int*)d_in[4];
    float*       out         = (float*)d_out;

    int E = in_sizes[1] / D_DIM;
    int P = out_size;

    {
        int threads = 256;
        int blocks = (E + threads - 1) / threads;
        precompute_dots_kernel<<<blocks, threads>>>(edge_attr, edge_vector, E);
    }

    int Pq = P / 4;
    if (Pq > 0) {
        int blocks = (Pq + BLOCK - 1) / BLOCK;
        pair_reduce_kernel4<<<blocks, BLOCK>>>(path_edges, path_len, out, Pq);
    }
    int done = Pq * 4;
    if (done < P) {
        int rem = P - done;
        pair_reduce_tail<<<(rem + 255) / 256, 256>>>(path_edges, path_len, out, done, P);
    }
}